// round 3
// baseline (speedup 1.0000x reference)
#include <cuda_runtime.h>

#define NN 20000
#define NE 320000
#define FF 64
#define RR 8
#define HH 64
#define PP 5
#define TILE_E 32
#define NTILE (NE / TILE_E)

#define INV_SQRT3 0.5773502691896258f
#define INV_SQRT2 0.7071067811865476f

typedef unsigned long long u64;

// scratch (static __device__ — no allocations allowed)
__device__ float g_s1[NN * FF];
__device__ float g_v1[NN * FF * 3];
__device__ float g_As[NN * FF];
__device__ float g_Av[NN * FF * 3];

__device__ __forceinline__ u64 pack2(float lo, float hi) {
    u64 r; asm("mov.b64 %0, {%1,%2};" : "=l"(r) : "f"(lo), "f"(hi)); return r;
}
__device__ __forceinline__ void ffma2(u64& d, u64 a, u64 b) {
    asm("fma.rn.f32x2 %0, %1, %2, %0;" : "+l"(d) : "l"(a), "l"(b));
}
__device__ __forceinline__ float2 unpk(u64 v) {
    float lo, hi; asm("mov.b64 {%0,%1}, %2;" : "=f"(lo), "=f"(hi) : "l"(v));
    return make_float2(lo, hi);
}
__device__ __forceinline__ void red4(float* addr, float a, float b, float c, float d) {
    asm volatile("red.global.add.v4.f32 [%0], {%1,%2,%3,%4};"
                 :: "l"(__cvta_generic_to_global(addr)),
                    "f"(a), "f"(b), "f"(c), "f"(d) : "memory");
}

// ---------------------------------------------------------------------------
// Kernel A: s1 = s @ W_lin_s ; v1 = einsum(v, W_lin_v). Zero A_s/A_v.
// 8-node groups; each thread computes 2 nodes (nl, nl+4) for one channel g,
// reusing each weight LDS across both nodes (L1-wavefront bound kernel).
// dynamic smem: sW 32KB + sS 2KB + sV 32KB + sVo 6KB = 72KB
// ---------------------------------------------------------------------------
__global__ __launch_bounds__(256) void knodeA(
    const float* __restrict__ s, const float* __restrict__ v,
    const float* __restrict__ Wls, const float* __restrict__ Wlv)
{
    extern __shared__ float asm_[];
    float2* sW = (float2*)asm_;              // [FF*FF] {wls,wlv}
    float*  sS = asm_ + 2 * FF * FF;         // [8*FF]
    float4* sV = (float4*)(sS + 8 * FF);     // [8*FF] (x,y,z,pad)
    float* sVo = (float*)(sV + 8 * FF);      // [8*FF*3]

    for (int i = threadIdx.x; i < FF * FF; i += blockDim.x)
        sW[i] = make_float2(Wls[i], Wlv[i]);

    const int ngrp = NN / 8;
    for (int grp = blockIdx.x; grp < ngrp; grp += gridDim.x) {
        __syncthreads();
        int nbase = grp * 8;
        for (int i = threadIdx.x; i < 8 * FF; i += blockDim.x)
            sS[i] = s[nbase * FF + i];
        float* sVf = (float*)sV;
        for (int i = threadIdx.x; i < 8 * FF * 3; i += blockDim.x)
            sVf[(i / 3) * 4 + (i % 3)] = v[nbase * FF * 3 + i];
        __syncthreads();

        int nl = threadIdx.x >> 6, g = threadIdx.x & 63;
        const float* ps0 = sS + nl * FF;
        const float* ps1 = sS + (nl + 4) * FF;
        const float4* pv0 = sV + nl * FF;
        const float4* pv1 = sV + (nl + 4) * FF;
        float as0 = 0.f, ax0 = 0.f, ay0 = 0.f, az0 = 0.f;
        float as1 = 0.f, ax1 = 0.f, ay1 = 0.f, az1 = 0.f;
#pragma unroll 8
        for (int f = 0; f < FF; f++) {
            float2 w = sW[f * FF + g];
            float4 v0 = pv0[f];
            float4 v1 = pv1[f];
            as0 += ps0[f] * w.x;
            as1 += ps1[f] * w.x;
            ax0 += v0.x * w.y; ay0 += v0.y * w.y; az0 += v0.z * w.y;
            ax1 += v1.x * w.y; ay1 += v1.y * w.y; az1 += v1.z * w.y;
        }
        g_s1[(nbase + nl) * FF + g] = as0;
        g_s1[(nbase + nl + 4) * FF + g] = as1;
        sVo[nl * FF * 3 + g * 3 + 0] = ax0;
        sVo[nl * FF * 3 + g * 3 + 1] = ay0;
        sVo[nl * FF * 3 + g * 3 + 2] = az0;
        sVo[(nl + 4) * FF * 3 + g * 3 + 0] = ax1;
        sVo[(nl + 4) * FF * 3 + g * 3 + 1] = ay1;
        sVo[(nl + 4) * FF * 3 + g * 3 + 2] = az1;
        __syncthreads();
        for (int i = threadIdx.x; i < 8 * FF * 3; i += blockDim.x) {
            g_v1[nbase * FF * 3 + i] = sVo[i];
            g_Av[nbase * FF * 3 + i] = 0.f;
        }
        for (int i = threadIdx.x; i < 8 * FF; i += blockDim.x)
            g_As[nbase * FF + i] = 0.f;
    }
}

// ---------------------------------------------------------------------------
// Kernel B (edge): tiled register-blocked GEMM (FFMA2) + TP + vector scatter.
// Gather of s1/v1 is PREFETCHED into registers before the GEMM so the 64-step
// FFMA2 loop hides the random-access L2 latency.
// ---------------------------------------------------------------------------
__global__ __launch_bounds__(256, 2) void kedge(
    const float* __restrict__ Y1, const float* __restrict__ efg,
    const int* __restrict__ senders, const int* __restrict__ receivers,
    const float* __restrict__ W_rad1, const float* __restrict__ W_rad2)
{
    extern __shared__ float smem[];
    float* sW2 = smem;                       // 20480 floats: [j][320]
    float* sW1 = sW2 + HH * PP * FF;         // 512: [j][8] transposed
    float* sh  = sW1 + 512;                  // 2048: [j][32]
    float* sY  = sh + HH * TILE_E;           // 96
    int* sSnd  = (int*)(sY + 96);            // 32
    int* sRcv  = sSnd + TILE_E;              // 32

    const int tid = threadIdx.x;
    for (int i = tid; i < HH * PP * FF; i += 256)
        sW2[i] = W_rad2[i];
    for (int i = tid; i < RR * HH; i += 256) {
        int r = i / HH, j = i % HH;
        sW1[j * RR + r] = W_rad1[i];
    }

    const int lane_e = tid & 31;   // edge slot for phase A
    const int oct = tid >> 5;      // j-octave for phase A
    const int eg = tid & 15;       // edge-group (2 edges) for GEMM
    const int fg = tid >> 4;       // f-group (4 channels)

    for (int tile = blockIdx.x; tile < NTILE; tile += gridDim.x) {
        __syncthreads();
        // ---- edge meta ----
        if (tid < TILE_E) {
            sSnd[tid] = senders[tile * TILE_E + tid];
            sRcv[tid] = receivers[tile * TILE_E + tid];
        }
        if (tid >= 128 && tid < 128 + 3 * TILE_E)
            sY[tid - 128] = Y1[tile * 3 * TILE_E + (tid - 128)];
        __syncthreads();

        // ---- prefetch sender gathers (consumed in phase C, after GEMM) ----
        int snd0 = sSnd[eg * 2 + 0];
        int snd1 = sSnd[eg * 2 + 1];
        float4 ss0 = *(const float4*)(g_s1 + snd0 * FF + fg * 4);
        float4 ss1 = *(const float4*)(g_s1 + snd1 * FF + fg * 4);
        const float* vp0 = g_v1 + snd0 * FF * 3 + fg * 12;
        const float* vp1 = g_v1 + snd1 * FF * 3 + fg * 12;
        float4 va0 = *(const float4*)(vp0);
        float4 vb0 = *(const float4*)(vp0 + 4);
        float4 vc0 = *(const float4*)(vp0 + 8);
        float4 va1 = *(const float4*)(vp1);
        float4 vb1 = *(const float4*)(vp1 + 4);
        float4 vc1 = *(const float4*)(vp1 + 8);

        // ---- phase A: h = silu(ef @ W1), each thread 8 j-values ----
        {
            int e = tile * TILE_E + lane_e;
            float4 ef0 = *(const float4*)(efg + e * RR);
            float4 ef1 = *(const float4*)(efg + e * RR + 4);
#pragma unroll
            for (int jj = 0; jj < 8; jj++) {
                int j = oct * 8 + jj;
                const float4* w = (const float4*)(sW1 + j * RR);
                float4 wa = w[0], wb = w[1];
                float x = ef0.x * wa.x + ef0.y * wa.y + ef0.z * wa.z + ef0.w * wa.w +
                          ef1.x * wb.x + ef1.y * wb.y + ef1.z * wb.z + ef1.w * wb.w;
                sh[j * TILE_E + lane_e] = __fdividef(x, 1.f + __expf(-x));
            }
        }
        __syncthreads();

        // ---- phase B: tw = h @ W2, FFMA2 register-blocked ----
        u64 acc[2][5][2];
#pragma unroll
        for (int a = 0; a < 2; a++)
#pragma unroll
            for (int p = 0; p < 5; p++) {
                acc[a][p][0] = 0ull; acc[a][p][1] = 0ull;
            }
        {
            const float* hrow = sh + eg * 2;
            const float* wrow = sW2 + fg * 4;
#pragma unroll 4
            for (int j = 0; j < HH; j++) {
                float2 h2 = *(const float2*)(hrow + j * TILE_E);
                u64 h0 = pack2(h2.x, h2.x);
                u64 h1 = pack2(h2.y, h2.y);
                const float* wj = wrow + j * (PP * FF);
#pragma unroll
                for (int p = 0; p < 5; p++) {
                    ulonglong2 w = *(const ulonglong2*)(wj + p * FF);
                    ffma2(acc[0][p][0], w.x, h0);
                    ffma2(acc[0][p][1], w.y, h0);
                    ffma2(acc[1][p][0], w.x, h1);
                    ffma2(acc[1][p][1], w.y, h1);
                }
            }
        }

        // ---- phase C: CG tensor product + vector scatter ----
#pragma unroll
        for (int e2 = 0; e2 < 2; e2++) {
            int le = eg * 2 + e2;
            int rcv = sRcv[le];
            float Yx = sY[le * 3 + 0], Yy = sY[le * 3 + 1], Yz = sY[le * 3 + 2];
            float4 ss = e2 ? ss1 : ss0;
            float4 va = e2 ? va1 : va0;
            float4 vb = e2 ? vb1 : vb0;
            float4 vc = e2 ? vc1 : vc0;

            float tw[5][4];
#pragma unroll
            for (int p = 0; p < 5; p++) {
                float2 a = unpk(acc[e2][p][0]);
                float2 b = unpk(acc[e2][p][1]);
                tw[p][0] = a.x; tw[p][1] = a.y; tw[p][2] = b.x; tw[p][3] = b.y;
            }
            float ssf[4] = {ss.x, ss.y, ss.z, ss.w};
            float vx[4] = {va.x, va.w, vb.z, vc.y};
            float vy[4] = {va.y, vb.x, vb.w, vc.z};
            float vz[4] = {va.z, vb.y, vc.x, vc.w};
            float ms[4], mvx[4], mvy[4], mvz[4];
#pragma unroll
            for (int f = 0; f < 4; f++) {
                float dot = vx[f] * Yx + vy[f] * Yy + vz[f] * Yz;
                float cx = vy[f] * Yz - vz[f] * Yy;
                float cy = vz[f] * Yx - vx[f] * Yz;
                float cz = vx[f] * Yy - vy[f] * Yx;
                ms[f] = tw[0][f] * ssf[f] + tw[1][f] * dot * INV_SQRT3;
                float t2s = tw[2][f] * ssf[f];
                float t4 = tw[4][f] * INV_SQRT2;
                mvx[f] = t2s * Yx + tw[3][f] * vx[f] + t4 * cx;
                mvy[f] = t2s * Yy + tw[3][f] * vy[f] + t4 * cy;
                mvz[f] = t2s * Yz + tw[3][f] * vz[f] + t4 * cz;
            }
            red4(g_As + rcv * FF + fg * 4, ms[0], ms[1], ms[2], ms[3]);
            float* avp = g_Av + rcv * FF * 3 + fg * 12;
            red4(avp + 0, mvx[0], mvy[0], mvz[0], mvx[1]);
            red4(avp + 4, mvy[1], mvz[1], mvx[2], mvy[2]);
            red4(avp + 8, mvz[2], mvx[3], mvy[3], mvz[3]);
        }
    }
}

// ---------------------------------------------------------------------------
// Kernel C: node post: W_int + species skip + product basis + W_prod + readout
// ---------------------------------------------------------------------------
__global__ __launch_bounds__(256, 2) void knodeC(
    const float* __restrict__ s, const float* __restrict__ v,
    const int* __restrict__ spec,
    const float* __restrict__ W_sc_s, const float* __restrict__ W_sc_v,
    const float* __restrict__ W_int_s, const float* __restrict__ W_int_v,
    const float* __restrict__ w_prod_s, const float* __restrict__ w_prod_v,
    const float* __restrict__ W_prod_s, const float* __restrict__ W_prod_v,
    const float* __restrict__ W_read,
    float* __restrict__ out_node, float* __restrict__ out_s,
    float* __restrict__ out_v)
{
    extern __shared__ float sm[];
    float* sWis = sm;
    float* sWiv = sWis + FF * FF;
    float* sWps = sWiv + FF * FF;
    float* sWpv = sWps + FF * FF;
    float* sWr  = sWpv + FF * FF;
    float* sAs  = sWr + FF;
    float* sAv  = sAs + 4 * FF;
    float* sSin = sAv + 4 * FF * 3;
    float* sVin = sSin + 4 * FF;
    float* sBs  = sVin + 4 * FF * 3;
    float* sBv  = sBs + 4 * FF;
    float* sRed = sBv + 4 * FF * 3;
    __shared__ int sSpec[4];

    for (int i = threadIdx.x; i < FF * FF; i += blockDim.x) {
        sWis[i] = W_int_s[i];
        sWiv[i] = W_int_v[i];
        sWps[i] = W_prod_s[i];
        sWpv[i] = W_prod_v[i];
    }
    if (threadIdx.x < FF) sWr[threadIdx.x] = W_read[threadIdx.x];

    const int ngrp = NN / 4;
    for (int grp = blockIdx.x; grp < ngrp; grp += gridDim.x) {
        __syncthreads();
        int nbase = grp * 4;
        for (int i = threadIdx.x; i < 4 * FF; i += blockDim.x) {
            sAs[i] = g_As[nbase * FF + i];
            sSin[i] = s[nbase * FF + i];
        }
        for (int i = threadIdx.x; i < 4 * FF * 3; i += blockDim.x) {
            sAv[i] = g_Av[nbase * FF * 3 + i];
            sVin[i] = v[nbase * FF * 3 + i];
        }
        if (threadIdx.x < 4) sSpec[threadIdx.x] = spec[nbase + threadIdx.x];
        __syncthreads();

        int nl = threadIdx.x >> 6, g = threadIdx.x & 63;
        int n = nbase + nl;
        int sp = sSpec[nl];
        const float* Wscs = W_sc_s + sp * FF * FF;
        const float* Wscv = W_sc_v + sp * FF * FF;
        const float* pAs = sAs + nl * FF;
        const float* pAv = sAv + nl * FF * 3;
        const float* pS = sSin + nl * FF;
        const float* pV = sVin + nl * FF * 3;

        float as = 0.f, avx = 0.f, avy = 0.f, avz = 0.f;
        float scs = 0.f, scvx = 0.f, scvy = 0.f, scvz = 0.f;
#pragma unroll 4
        for (int f = 0; f < FF; f++) {
            float wis = sWis[f * FF + g], wiv = sWiv[f * FF + g];
            float wss = __ldg(Wscs + f * FF + g);
            float wsv = __ldg(Wscv + f * FF + g);
            as += pAs[f] * wis;
            avx += pAv[f * 3 + 0] * wiv;
            avy += pAv[f * 3 + 1] * wiv;
            avz += pAv[f * 3 + 2] * wiv;
            scs += pS[f] * wss;
            scvx += pV[f * 3 + 0] * wsv;
            scvy += pV[f * 3 + 1] * wsv;
            scvz += pV[f * 3 + 2] * wsv;
        }
        const float inv = 0.25f;
        as *= inv; avx *= inv; avy *= inv; avz *= inv;

        const float* wps = w_prod_s + sp * 5 * FF;
        const float* wpv = w_prod_v + sp * 4 * FF;
        float d = avx * avx + avy * avy + avz * avz;
        float as2 = as * as;
        float Bs = wps[0 * FF + g] * as + wps[1 * FF + g] * as2 +
                   wps[2 * FF + g] * d + wps[3 * FF + g] * as2 * as +
                   wps[4 * FF + g] * as * d;
        float gv = wpv[0 * FF + g] + wpv[1 * FF + g] * as +
                   wpv[2 * FF + g] * as2 + wpv[3 * FF + g] * d;
        sBs[nl * FF + g] = Bs;
        sBv[nl * FF * 3 + g * 3 + 0] = gv * avx;
        sBv[nl * FF * 3 + g * 3 + 1] = gv * avy;
        sBv[nl * FF * 3 + g * 3 + 2] = gv * avz;
        __syncthreads();

        const float* pBs = sBs + nl * FF;
        const float* pBv = sBv + nl * FF * 3;
        float so = scs, vox = scvx, voy = scvy, voz = scvz;
#pragma unroll 4
        for (int f = 0; f < FF; f++) {
            float wp = sWps[f * FF + g], wv = sWpv[f * FF + g];
            so += pBs[f] * wp;
            vox += pBv[f * 3 + 0] * wv;
            voy += pBv[f * 3 + 1] * wv;
            voz += pBv[f * 3 + 2] * wv;
        }
        out_s[n * FF + g] = so;
        out_v[n * FF * 3 + g * 3 + 0] = vox;
        out_v[n * FF * 3 + g * 3 + 1] = voy;
        out_v[n * FF * 3 + g * 3 + 2] = voz;

        float r = so * sWr[g];
#pragma unroll
        for (int o = 16; o > 0; o >>= 1) r += __shfl_down_sync(0xffffffffu, r, o);
        if ((threadIdx.x & 31) == 0) sRed[threadIdx.x >> 5] = r;
        __syncthreads();
        if ((threadIdx.x & 63) == 0)
            out_node[n] = sRed[threadIdx.x >> 5] + sRed[(threadIdx.x >> 5) + 1];
    }
}

// ---------------------------------------------------------------------------
extern "C" void kernel_launch(void* const* d_in, const int* in_sizes, int n_in,
                              void* d_out, int out_size)
{
    const float* s    = (const float*)d_in[0];
    const float* v    = (const float*)d_in[1];
    const float* Y1   = (const float*)d_in[2];
    const float* ef   = (const float*)d_in[3];
    const int*   spec = (const int*)d_in[4];
    const int*   snd  = (const int*)d_in[5];
    const int*   rcv  = (const int*)d_in[6];
    const float* Wls  = (const float*)d_in[7];
    const float* Wlv  = (const float*)d_in[8];
    const float* Wscs = (const float*)d_in[9];
    const float* Wscv = (const float*)d_in[10];
    const float* Wr1  = (const float*)d_in[11];
    const float* Wr2  = (const float*)d_in[12];
    const float* Wis  = (const float*)d_in[13];
    const float* Wiv  = (const float*)d_in[14];
    const float* wps  = (const float*)d_in[15];
    const float* wpv  = (const float*)d_in[16];
    const float* Wps  = (const float*)d_in[17];
    const float* Wpv  = (const float*)d_in[18];
    const float* Wrd  = (const float*)d_in[19];

    float* out = (float*)d_out;
    float* out_node = out;
    float* out_s = out + NN;
    float* out_v = out + NN + NN * FF;

    const int smemA = (2 * FF * FF + 8 * FF + 8 * FF * 4 + 8 * FF * 3) *
                      (int)sizeof(float);  // 73728 B
    const int smemB = (HH * PP * FF + 512 + HH * TILE_E + 96 + 2 * TILE_E) *
                      (int)sizeof(float);  // 92928 B
    const int smemC = (4 * FF * FF + FF + 4 * FF * 2 + 4 * FF * 3 * 2 +
                       4 * FF + 4 * FF * 3 + 8) * (int)sizeof(float);
    cudaFuncSetAttribute(knodeA, cudaFuncAttributeMaxDynamicSharedMemorySize, smemA);
    cudaFuncSetAttribute(kedge, cudaFuncAttributeMaxDynamicSharedMemorySize, smemB);
    cudaFuncSetAttribute(knodeC, cudaFuncAttributeMaxDynamicSharedMemorySize, smemC);

    knodeA<<<296, 256, smemA>>>(s, v, Wls, Wlv);
    kedge<<<296, 256, smemB>>>(Y1, ef, snd, rcv, Wr1, Wr2);
    knodeC<<<296, 256, smemC>>>(s, v, spec, Wscs, Wscv, Wis, Wiv,
                                wps, wpv, Wps, Wpv, Wrd,
                                out_node, out_s, out_v);
}

// round 5
// speedup vs baseline: 1.3022x; 1.3022x over previous
#include <cuda_runtime.h>
#include <cuda_bf16.h>
#include <cstdint>

#define NN 20000
#define NE 320000
#define FF 64
#define RR 8
#define HH 64
#define PP 5
#define TILE 64
#define NTILES (NE / TILE)

#define INV_SQRT3 0.5773502691896258f
#define INV_SQRT2 0.7071067811865476f

// scratch (static __device__ — no allocations allowed)
__device__ float g_s1[NN * FF];
__device__ float g_v1[NN * FF * 3];
__device__ float g_As[NN * FF];
__device__ float g_Av[NN * FF * 3];

// ---------------------------------------------------------------------------
__device__ __forceinline__ void red4(float* addr, float a, float b, float c, float d) {
    asm volatile("red.global.add.v4.f32 [%0], {%1,%2,%3,%4};"
                 :: "l"(__cvta_generic_to_global(addr)),
                    "f"(a), "f"(b), "f"(c), "f"(d) : "memory");
}
__device__ __forceinline__ uint32_t smem_u32(const void* p) {
    uint32_t a;
    asm("{ .reg .u64 t; cvta.to.shared.u64 t, %1; cvt.u32.u64 %0, t; }"
        : "=r"(a) : "l"(p));
    return a;
}
__device__ __forceinline__ void ldsm_x4(uint32_t* r, uint32_t addr) {
    asm volatile("ldmatrix.sync.aligned.m8n8.x4.shared.b16 {%0,%1,%2,%3}, [%4];"
                 : "=r"(r[0]), "=r"(r[1]), "=r"(r[2]), "=r"(r[3]) : "r"(addr));
}
__device__ __forceinline__ void ldsm_x4t(uint32_t* r, uint32_t addr) {
    asm volatile("ldmatrix.sync.aligned.m8n8.x4.trans.shared.b16 {%0,%1,%2,%3}, [%4];"
                 : "=r"(r[0]), "=r"(r[1]), "=r"(r[2]), "=r"(r[3]) : "r"(addr));
}
__device__ __forceinline__ void mma16816(float* c, const uint32_t* a, const uint32_t* b) {
    asm volatile("mma.sync.aligned.m16n8k16.row.col.f32.bf16.bf16.f32 "
                 "{%0,%1,%2,%3}, {%4,%5,%6,%7}, {%8,%9}, {%0,%1,%2,%3};"
                 : "+f"(c[0]), "+f"(c[1]), "+f"(c[2]), "+f"(c[3])
                 : "r"(a[0]), "r"(a[1]), "r"(a[2]), "r"(a[3]),
                   "r"(b[0]), "r"(b[1]));
}

// smem layout (byte offsets into dynamic smem)
#define ASTRIDE 72      // bf16 per A row (144B, conflict-free ldmatrix)
#define BSTRIDE 328     // bf16 per B row (656B, conflict-free ldmatrix)
#define TWSTRIDE 72     // floats per tw row (conflict-free float2 stores)
#define OFF_W1   0                           // 512 floats      (2048 B)
#define OFF_BHI  2048                        // 64*328*2      = 41984 B
#define OFF_BLO  (OFF_BHI + 41984)
#define OFF_AHI  (OFF_BLO + 41984)           // 64*72*2       = 9216 B
#define OFF_ALO  (OFF_AHI + 9216)
#define OFF_TW   (OFF_ALO + 9216)            // 5*64*72*4     = 92160 B
#define DYN_BYTES (OFF_TW + 92160)           // 196608 B

// ---------------------------------------------------------------------------
// Kernel A: s1 = s @ W_lin_s ; v1 = einsum(v, W_lin_v). Zero A_s/A_v.
// ---------------------------------------------------------------------------
__global__ __launch_bounds__(256) void knodeA(
    const float* __restrict__ s, const float* __restrict__ v,
    const float* __restrict__ Wls, const float* __restrict__ Wlv)
{
    __shared__ float sWls[FF * FF], sWlv[FF * FF];
    __shared__ float sS[4 * FF], sV[4 * FF * 3];
    for (int i = threadIdx.x; i < FF * FF; i += blockDim.x) {
        sWls[i] = Wls[i];
        sWlv[i] = Wlv[i];
    }
    const int ngrp = NN / 4;
    for (int grp = blockIdx.x; grp < ngrp; grp += gridDim.x) {
        __syncthreads();
        int nbase = grp * 4;
        for (int i = threadIdx.x; i < 4 * FF; i += blockDim.x)
            sS[i] = s[nbase * FF + i];
        for (int i = threadIdx.x; i < 4 * FF * 3; i += blockDim.x)
            sV[i] = v[nbase * FF * 3 + i];
        __syncthreads();
        int nl = threadIdx.x >> 6, g = threadIdx.x & 63;
        int n = nbase + nl;
        const float* ps = sS + nl * FF;
        const float* pv = sV + nl * FF * 3;
        float as = 0.f, ax = 0.f, ay = 0.f, az = 0.f;
#pragma unroll 8
        for (int f = 0; f < FF; f++) {
            float wls = sWls[f * FF + g], wlv = sWlv[f * FF + g];
            as += ps[f] * wls;
            ax += pv[f * 3 + 0] * wlv;
            ay += pv[f * 3 + 1] * wlv;
            az += pv[f * 3 + 2] * wlv;
        }
        g_s1[n * FF + g] = as;
        g_v1[n * FF * 3 + g * 3 + 0] = ax;
        g_v1[n * FF * 3 + g * 3 + 1] = ay;
        g_v1[n * FF * 3 + g * 3 + 2] = az;
        g_As[n * FF + g] = 0.f;
        g_Av[n * FF * 3 + g * 3 + 0] = 0.f;
        g_Av[n * FF * 3 + g * 3 + 1] = 0.f;
        g_Av[n * FF * 3 + g * 3 + 2] = 0.f;
    }
}

// ---------------------------------------------------------------------------
// Kernel B: tensor-core (mma.sync bf16, hi/lo 3-pass) radial GEMM per 64-edge
// tile + CG tensor product + red.v4 scatter. Persistent, 1 block/SM.
// ---------------------------------------------------------------------------
__global__ __launch_bounds__(256, 1) void kedge3(
    const float* __restrict__ Y1, const float* __restrict__ efg,
    const int* __restrict__ senders, const int* __restrict__ receivers,
    const float* __restrict__ W_rad1, const float* __restrict__ W_rad2)
{
    extern __shared__ char dsm[];
    float* sW1 = (float*)(dsm + OFF_W1);     // [j][8] transposed
    float* twp = (float*)(dsm + OFF_TW);     // [5][64][72]
    const uint32_t uBhi = smem_u32(dsm + OFF_BHI);
    const uint32_t uBlo = smem_u32(dsm + OFF_BLO);
    const uint32_t uAhi = smem_u32(dsm + OFF_AHI);
    const uint32_t uAlo = smem_u32(dsm + OFF_ALO);

    const int tid = threadIdx.x, wid = tid >> 5, lane = tid & 31;

    // --- one-time staging: W1 transposed, W2 -> B hi/lo [64][328] bf16 ---
    for (int i = tid; i < RR * HH; i += 256) {
        int r = i / HH, j = i % HH;
        sW1[j * RR + r] = W_rad1[i];
    }
    for (int i = tid; i < HH * (PP * FF / 2); i += 256) {
        int k = i / 160, n2 = i % 160;
        float w0 = W_rad2[k * (PP * FF) + 2 * n2];
        float w1 = W_rad2[k * (PP * FF) + 2 * n2 + 1];
        __nv_bfloat16 h0 = __float2bfloat16(w0);
        __nv_bfloat16 h1 = __float2bfloat16(w1);
        __nv_bfloat16 l0 = __float2bfloat16(w0 - __bfloat162float(h0));
        __nv_bfloat16 l1 = __float2bfloat16(w1 - __bfloat162float(h1));
        uint32_t off = (uint32_t)(k * BSTRIDE + 2 * n2) * 2;
        __nv_bfloat162 ph; ph.x = h0; ph.y = h1;
        __nv_bfloat162 pl; pl.x = l0; pl.y = l1;
        *(__nv_bfloat162*)(dsm + OFF_BHI + off) = ph;
        *(__nv_bfloat162*)(dsm + OFF_BLO + off) = pl;
    }
    __syncthreads();

    // MMA geometry: warp -> 16 edges (eg) x 160 cols (ch)
    const int eg = wid & 3, ch = wid >> 2;
    const int ebw = eg * 16;            // edge base within tile
    const int cbase = ch * 160;         // column base
    const int lm = lane >> 3, lr = lane & 7;   // ldmatrix lane mapping
    const int arow = ebw + (lm & 1) * 8 + lr;  // A: row within tile
    const int acol0 = (lm >> 1) * 8;           // A: col offset within k-step
    const int brow0 = (lm & 1) * 8 + lr;       // B: row offset within k-step
    const int qq = lane & 3, eh = lane >> 2;   // accum store mapping

    // epilogue mapping: thread -> edge e (tid>>2), f-quarter q
    const int ee = tid >> 2, fq = tid & 3, f0 = fq * 16;

    for (int t = blockIdx.x; t < NTILES; t += gridDim.x) {
        const int ebase = t * TILE;

        // ---- stage A: h = silu(ef @ W1) -> bf16 hi/lo [64][72] ----
        {
            int e = tid & 63, jq = tid >> 6;
            const float4* efp = (const float4*)(efg + (size_t)(ebase + e) * RR);
            float4 F0 = efp[0], F1 = efp[1];
#pragma unroll
            for (int jj = 0; jj < 16; jj += 2) {
                int j = jq * 16 + jj;
                const float4* wA = (const float4*)(sW1 + j * RR);
                float4 a0 = wA[0], a1 = wA[1], b0 = wA[2], b1 = wA[3];
                float z0 = F0.x * a0.x + F0.y * a0.y + F0.z * a0.z + F0.w * a0.w +
                           F1.x * a1.x + F1.y * a1.y + F1.z * a1.z + F1.w * a1.w;
                float z1 = F0.x * b0.x + F0.y * b0.y + F0.z * b0.z + F0.w * b0.w +
                           F1.x * b1.x + F1.y * b1.y + F1.z * b1.z + F1.w * b1.w;
                float h0f = __fdividef(z0, 1.f + __expf(-z0));
                float h1f = __fdividef(z1, 1.f + __expf(-z1));
                __nv_bfloat16 h0 = __float2bfloat16(h0f);
                __nv_bfloat16 h1 = __float2bfloat16(h1f);
                __nv_bfloat16 l0 = __float2bfloat16(h0f - __bfloat162float(h0));
                __nv_bfloat16 l1 = __float2bfloat16(h1f - __bfloat162float(h1));
                uint32_t off = (uint32_t)(e * ASTRIDE + j) * 2;
                __nv_bfloat162 ph; ph.x = h0; ph.y = h1;
                __nv_bfloat162 pl; pl.x = l0; pl.y = l1;
                *(__nv_bfloat162*)(dsm + OFF_AHI + off) = ph;
                *(__nv_bfloat162*)(dsm + OFF_ALO + off) = pl;
            }
        }
        __syncthreads();

        // ---- GEMM: tw = h @ W2, 3 bf16 passes (hi*hi, hi*lo, lo*hi) ----
        {
            float acc[20][4];
#pragma unroll
            for (int n = 0; n < 20; n++) {
                acc[n][0] = 0.f; acc[n][1] = 0.f; acc[n][2] = 0.f; acc[n][3] = 0.f;
            }
            const uint32_t Asel[3] = {uAhi, uAhi, uAlo};
            const uint32_t Bsel[3] = {uBhi, uBlo, uBhi};
#pragma unroll
            for (int pass = 0; pass < 3; pass++) {
                uint32_t Ab = Asel[pass], Bb = Bsel[pass];
#pragma unroll
                for (int k = 0; k < 4; k++) {
                    uint32_t a[4];
                    ldsm_x4(a, Ab + (uint32_t)(arow * ASTRIDE + k * 16 + acol0) * 2);
#pragma unroll
                    for (int nt2 = 0; nt2 < 10; nt2++) {
                        uint32_t b[4];
                        ldsm_x4t(b, Bb + (uint32_t)((k * 16 + brow0) * BSTRIDE +
                                                    cbase + nt2 * 16 + acol0) * 2);
                        mma16816(acc[2 * nt2], a, b);
                        mma16816(acc[2 * nt2 + 1], a, b + 2);
                    }
                }
            }
            // store accumulators to tw[p][e][f] (padded, conflict-free)
#pragma unroll
            for (int nt = 0; nt < 20; nt++) {
                int c = cbase + nt * 8 + 2 * qq;
                int p = c >> 6, f = c & 63;
                float* dst = twp + (size_t)(p * 64 + ebw + eh) * TWSTRIDE + f;
                float2 lo; lo.x = acc[nt][0]; lo.y = acc[nt][1];
                float2 hi; hi.x = acc[nt][2]; hi.y = acc[nt][3];
                *(float2*)dst = lo;
                *(float2*)(dst + 8 * TWSTRIDE) = hi;
            }
        }
        __syncthreads();

        // ---- epilogue: CG tensor product + scatter (thread = edge x f-quad) --
        {
            int e = ebase + ee;
            int snd = senders[e], rcv = receivers[e];
            float Yx = Y1[e * 3 + 0], Yy = Y1[e * 3 + 1], Yz = Y1[e * 3 + 2];

            float4 T[5][4];
#pragma unroll
            for (int p = 0; p < 5; p++) {
                const float* tb = twp + (size_t)(p * 64 + ee) * TWSTRIDE + f0;
#pragma unroll
                for (int c4 = 0; c4 < 4; c4++)
                    T[p][c4] = *(const float4*)(tb + 4 * c4);
            }
            float4 S4[4];
            const float* sp = g_s1 + (size_t)snd * FF + f0;
#pragma unroll
            for (int c4 = 0; c4 < 4; c4++) S4[c4] = *(const float4*)(sp + 4 * c4);
            float4 V4[12];
            const float* vp = g_v1 + (size_t)snd * FF * 3 + f0 * 3;
#pragma unroll
            for (int i = 0; i < 12; i++) V4[i] = *(const float4*)(vp + 4 * i);

            const float* sf = (const float*)S4;
            const float* vvf = (const float*)V4;
            float* Ap = g_As + (size_t)rcv * FF + f0;
            float* Vp = g_Av + (size_t)rcv * FF * 3 + f0 * 3;

#pragma unroll
            for (int c4 = 0; c4 < 4; c4++) {
                float ms[4], mv[12];
#pragma unroll
                for (int i = 0; i < 4; i++) {
                    int fi = 4 * c4 + i;
                    float tw0 = ((const float*)T[0])[fi];
                    float tw1 = ((const float*)T[1])[fi];
                    float tw2 = ((const float*)T[2])[fi];
                    float tw3 = ((const float*)T[3])[fi];
                    float tw4 = ((const float*)T[4])[fi];
                    float ssf = sf[fi];
                    float vx = vvf[3 * fi + 0];
                    float vy = vvf[3 * fi + 1];
                    float vz = vvf[3 * fi + 2];
                    float dot = vx * Yx + vy * Yy + vz * Yz;
                    float cx = vy * Yz - vz * Yy;
                    float cy = vz * Yx - vx * Yz;
                    float cz = vx * Yy - vy * Yx;
                    ms[i] = tw0 * ssf + tw1 * dot * INV_SQRT3;
                    float t2s = tw2 * ssf;
                    float t4 = tw4 * INV_SQRT2;
                    mv[3 * i + 0] = t2s * Yx + tw3 * vx + t4 * cx;
                    mv[3 * i + 1] = t2s * Yy + tw3 * vy + t4 * cy;
                    mv[3 * i + 2] = t2s * Yz + tw3 * vz + t4 * cz;
                }
                red4(Ap + 4 * c4, ms[0], ms[1], ms[2], ms[3]);
                red4(Vp + 12 * c4 + 0, mv[0], mv[1], mv[2], mv[3]);
                red4(Vp + 12 * c4 + 4, mv[4], mv[5], mv[6], mv[7]);
                red4(Vp + 12 * c4 + 8, mv[8], mv[9], mv[10], mv[11]);
            }
        }
        __syncthreads();
    }
}

// ---------------------------------------------------------------------------
// Kernel C: node post: W_int + species skip + product basis + W_prod + readout
// ---------------------------------------------------------------------------
__global__ __launch_bounds__(256, 2) void knodeC(
    const float* __restrict__ s, const float* __restrict__ v,
    const int* __restrict__ spec,
    const float* __restrict__ W_sc_s, const float* __restrict__ W_sc_v,
    const float* __restrict__ W_int_s, const float* __restrict__ W_int_v,
    const float* __restrict__ w_prod_s, const float* __restrict__ w_prod_v,
    const float* __restrict__ W_prod_s, const float* __restrict__ W_prod_v,
    const float* __restrict__ W_read,
    float* __restrict__ out_node, float* __restrict__ out_s,
    float* __restrict__ out_v)
{
    extern __shared__ float sm[];
    float* sWis = sm;
    float* sWiv = sWis + FF * FF;
    float* sWps = sWiv + FF * FF;
    float* sWpv = sWps + FF * FF;
    float* sWr  = sWpv + FF * FF;
    float* sAs  = sWr + FF;
    float* sAv  = sAs + 4 * FF;
    float* sSin = sAv + 4 * FF * 3;
    float* sVin = sSin + 4 * FF;
    float* sBs  = sVin + 4 * FF * 3;
    float* sBv  = sBs + 4 * FF;
    float* sRed = sBv + 4 * FF * 3;
    __shared__ int sSpec[4];

    for (int i = threadIdx.x; i < FF * FF; i += blockDim.x) {
        sWis[i] = W_int_s[i];
        sWiv[i] = W_int_v[i];
        sWps[i] = W_prod_s[i];
        sWpv[i] = W_prod_v[i];
    }
    if (threadIdx.x < FF) sWr[threadIdx.x] = W_read[threadIdx.x];

    const int ngrp = NN / 4;
    for (int grp = blockIdx.x; grp < ngrp; grp += gridDim.x) {
        __syncthreads();
        int nbase = grp * 4;
        for (int i = threadIdx.x; i < 4 * FF; i += blockDim.x) {
            sAs[i] = g_As[nbase * FF + i];
            sSin[i] = s[nbase * FF + i];
        }
        for (int i = threadIdx.x; i < 4 * FF * 3; i += blockDim.x) {
            sAv[i] = g_Av[nbase * FF * 3 + i];
            sVin[i] = v[nbase * FF * 3 + i];
        }
        if (threadIdx.x < 4) sSpec[threadIdx.x] = spec[nbase + threadIdx.x];
        __syncthreads();

        int nl = threadIdx.x >> 6, g = threadIdx.x & 63;
        int n = nbase + nl;
        int sp = sSpec[nl];
        const float* Wscs = W_sc_s + sp * FF * FF;
        const float* Wscv = W_sc_v + sp * FF * FF;
        const float* pAs = sAs + nl * FF;
        const float* pAv = sAv + nl * FF * 3;
        const float* pS = sSin + nl * FF;
        const float* pV = sVin + nl * FF * 3;

        float as = 0.f, avx = 0.f, avy = 0.f, avz = 0.f;
        float scs = 0.f, scvx = 0.f, scvy = 0.f, scvz = 0.f;
#pragma unroll 4
        for (int f = 0; f < FF; f++) {
            float wis = sWis[f * FF + g], wiv = sWiv[f * FF + g];
            float wss = __ldg(Wscs + f * FF + g);
            float wsv = __ldg(Wscv + f * FF + g);
            as += pAs[f] * wis;
            avx += pAv[f * 3 + 0] * wiv;
            avy += pAv[f * 3 + 1] * wiv;
            avz += pAv[f * 3 + 2] * wiv;
            scs += pS[f] * wss;
            scvx += pV[f * 3 + 0] * wsv;
            scvy += pV[f * 3 + 1] * wsv;
            scvz += pV[f * 3 + 2] * wsv;
        }
        const float inv = 0.25f;
        as *= inv; avx *= inv; avy *= inv; avz *= inv;

        const float* wps = w_prod_s + sp * 5 * FF;
        const float* wpv = w_prod_v + sp * 4 * FF;
        float d = avx * avx + avy * avy + avz * avz;
        float as2 = as * as;
        float Bs = wps[0 * FF + g] * as + wps[1 * FF + g] * as2 +
                   wps[2 * FF + g] * d + wps[3 * FF + g] * as2 * as +
                   wps[4 * FF + g] * as * d;
        float gv = wpv[0 * FF + g] + wpv[1 * FF + g] * as +
                   wpv[2 * FF + g] * as2 + wpv[3 * FF + g] * d;
        sBs[nl * FF + g] = Bs;
        sBv[nl * FF * 3 + g * 3 + 0] = gv * avx;
        sBv[nl * FF * 3 + g * 3 + 1] = gv * avy;
        sBv[nl * FF * 3 + g * 3 + 2] = gv * avz;
        __syncthreads();

        const float* pBs = sBs + nl * FF;
        const float* pBv = sBv + nl * FF * 3;
        float so = scs, vox = scvx, voy = scvy, voz = scvz;
#pragma unroll 4
        for (int f = 0; f < FF; f++) {
            float wp = sWps[f * FF + g], wv = sWpv[f * FF + g];
            so += pBs[f] * wp;
            vox += pBv[f * 3 + 0] * wv;
            voy += pBv[f * 3 + 1] * wv;
            voz += pBv[f * 3 + 2] * wv;
        }
        out_s[n * FF + g] = so;
        out_v[n * FF * 3 + g * 3 + 0] = vox;
        out_v[n * FF * 3 + g * 3 + 1] = voy;
        out_v[n * FF * 3 + g * 3 + 2] = voz;

        float r = so * sWr[g];
#pragma unroll
        for (int o = 16; o > 0; o >>= 1) r += __shfl_down_sync(0xffffffffu, r, o);
        if ((threadIdx.x & 31) == 0) sRed[threadIdx.x >> 5] = r;
        __syncthreads();
        if ((threadIdx.x & 63) == 0)
            out_node[n] = sRed[threadIdx.x >> 5] + sRed[(threadIdx.x >> 5) + 1];
    }
}

// ---------------------------------------------------------------------------
extern "C" void kernel_launch(void* const* d_in, const int* in_sizes, int n_in,
                              void* d_out, int out_size)
{
    const float* s    = (const float*)d_in[0];
    const float* v    = (const float*)d_in[1];
    const float* Y1   = (const float*)d_in[2];
    const float* ef   = (const float*)d_in[3];
    const int*   spec = (const int*)d_in[4];
    const int*   snd  = (const int*)d_in[5];
    const int*   rcv  = (const int*)d_in[6];
    const float* Wls  = (const float*)d_in[7];
    const float* Wlv  = (const float*)d_in[8];
    const float* Wscs = (const float*)d_in[9];
    const float* Wscv = (const float*)d_in[10];
    const float* Wr1  = (const float*)d_in[11];
    const float* Wr2  = (const float*)d_in[12];
    const float* Wis  = (const float*)d_in[13];
    const float* Wiv  = (const float*)d_in[14];
    const float* wps  = (const float*)d_in[15];
    const float* wpv  = (const float*)d_in[16];
    const float* Wps  = (const float*)d_in[17];
    const float* Wpv  = (const float*)d_in[18];
    const float* Wrd  = (const float*)d_in[19];

    float* out = (float*)d_out;
    float* out_node = out;
    float* out_s = out + NN;
    float* out_v = out + NN + NN * FF;

    const int smemC = (4 * FF * FF + FF + 4 * FF * 2 + 4 * FF * 3 * 2 +
                       4 * FF + 4 * FF * 3 + 8) * (int)sizeof(float);
    cudaFuncSetAttribute(kedge3, cudaFuncAttributeMaxDynamicSharedMemorySize, DYN_BYTES);
    cudaFuncSetAttribute(knodeC, cudaFuncAttributeMaxDynamicSharedMemorySize, smemC);

    knodeA<<<592, 256>>>(s, v, Wls, Wlv);
    kedge3<<<152, 256, DYN_BYTES>>>(Y1, ef, snd, rcv, Wr1, Wr2);
    knodeC<<<296, 256, smemC>>>(s, v, spec, Wscs, Wscv, Wis, Wiv,
                                wps, wpv, Wps, Wpv, Wrd,
                                out_node, out_s, out_v);
}